// round 9
// baseline (speedup 1.0000x reference)
#include <cuda_runtime.h>
#include <cuda_bf16.h>

// ---------------------------------------------------------------------------
// MultiCrossTransformer on GB300 (sm_103a), fp32 with f32x2 packed FMA.
//
// Pipeline:
//  1) fuse_kernel : WF[k][d] = sum_c proj[d][c] * w_ms[c][k]   (k = ci*9+kh*3+kw)
//  2) conv_kernel : feats[img][d][400] = conv3x3_s2(img, WF)   (208 imgs, 256 d)
//  3) gemm1       : sim[bk][m][j] = scale * sum_d Q[d][m] K[d][j]
//  4) softmax     : row softmax over j (2000)
//  5) gemm2       : Ot[bk][c][m] = sum_j V[c][j] attn[m][j]
//  6) dist        : out[bk] = -sum (qv - Ot)^2 / 400
// ---------------------------------------------------------------------------

typedef unsigned long long ull;

#define IC    512
#define HH    41
#define WW    41
#define OHW   20
#define NPOS  400           // 20*20
#define OC    256           // 128 qk-proj + 128 v-proj
#define NIMG  208
#define FSTRIDE 102400      // 256*400 floats per image
#define NKEY  2000          // n*400
#define NBK   40

// scratch (device globals; no allocation APIs)
__device__ float g_WF[4608 * 256];             // [k][d]
__device__ float g_feats[(size_t)NIMG * OC * NPOS];
__device__ float g_sim[(size_t)NBK * NPOS * NKEY];
__device__ float g_Ot[(size_t)NBK * 128 * NPOS];

// ---------------- f32x2 helpers ----------------
__device__ __forceinline__ void ffma2(ull& d, ull a, ull b) {
    asm("fma.rn.f32x2 %0, %1, %2, %0;" : "+l"(d) : "l"(a), "l"(b));
}
__device__ __forceinline__ ull pack2(float x, float y) {
    ull r; asm("mov.b64 %0, {%1, %2};" : "=l"(r) : "f"(x), "f"(y)); return r;
}

// ---------------- 1) weight fusion ----------------
// grid 288, block 256.  Each block: 16 consecutive k, 256 d.
__global__ void __launch_bounds__(256) fuse_kernel(
    const float* __restrict__ w_qk, const float* __restrict__ w_v,
    const float* __restrict__ w_ms)
{
    __shared__ __align__(16) float wcol[512 * 16];   // [c][t]
    int k0 = blockIdx.x * 16;
    int d  = threadIdx.x;

    for (int e = d; e < 512 * 16; e += 256) {
        int c = e >> 4, t = e & 15;
        wcol[e] = w_ms[(size_t)c * 4608 + k0 + t];
    }
    __syncthreads();

    const float4* proj4 = (const float4*)((d < 128) ? (w_qk + (size_t)d * 512)
                                                    : (w_v  + (size_t)(d - 128) * 512));
    float acc[16];
#pragma unroll
    for (int t = 0; t < 16; t++) acc[t] = 0.f;

    for (int c4 = 0; c4 < 128; c4++) {
        float4 p = proj4[c4];
#pragma unroll
        for (int q = 0; q < 4; q++) {
            float pv = (q == 0) ? p.x : (q == 1) ? p.y : (q == 2) ? p.z : p.w;
            const float4* wf = (const float4*)(wcol + (c4 * 4 + q) * 16);
            float4 b0 = wf[0], b1 = wf[1], b2 = wf[2], b3 = wf[3];
            acc[0]  += pv * b0.x;  acc[1]  += pv * b0.y;
            acc[2]  += pv * b0.z;  acc[3]  += pv * b0.w;
            acc[4]  += pv * b1.x;  acc[5]  += pv * b1.y;
            acc[6]  += pv * b1.z;  acc[7]  += pv * b1.w;
            acc[8]  += pv * b2.x;  acc[9]  += pv * b2.y;
            acc[10] += pv * b2.z;  acc[11] += pv * b2.w;
            acc[12] += pv * b3.x;  acc[13] += pv * b3.y;
            acc[14] += pv * b3.z;  acc[15] += pv * b3.w;
        }
    }
#pragma unroll
    for (int t = 0; t < 16; t++)
        g_WF[(size_t)(k0 + t) * 256 + d] = acc[t];
}

// ---------------- 2) conv 3x3 stride-2 (fused 256 out ch) ----------------
// grid (5 row-tiles, 4 d-tiles, 208 imgs), block 128.
// SMEM input rows stored parity-split so stride-2 column pairs are one LDS.64:
//   evenA[i] = col 2i (i 0..20) at +0
//   odd  [i] = col 2i+1 (i 0..19) at +22
//   evenB[i] = col 2i+2 (i 0..19) at +44
#define CI_CHUNK 8
#define XROW 76
#define EAOF 0
#define ODOF 22
#define EBOF 44

__global__ void __launch_bounds__(128) conv_kernel(
    const float* __restrict__ img_query, const float* __restrict__ img_supports)
{
    __shared__ __align__(16) float wS[72 * 64];
    __shared__ __align__(16) float xS[CI_CHUNK * 9 * XROW];

    const int rt  = blockIdx.x;             // 0..4
    const int dt  = blockIdx.y;             // 0..3
    const int img = blockIdx.z;             // 0..207
    const float* src = (img < 8) ? (img_query + (size_t)img * IC * HH * WW)
                                 : (img_supports + (size_t)(img - 8) * IC * HH * WW);
    const int r0  = rt * 4;
    const int tid = threadIdx.x;
    const int dg  = tid >> 3;               // 0..15  -> d_local = dg*4
    const int pg  = tid & 7;
    const int r_loc = pg >> 1;              // 0..3
    const int pb    = (pg & 1) * 5;         // pair base (pairs pb..pb+4)

    ull acc[4][5];
#pragma unroll
    for (int i = 0; i < 4; i++)
#pragma unroll
        for (int j = 0; j < 5; j++) acc[i][j] = 0ULL;

    for (int ci0 = 0; ci0 < IC; ci0 += CI_CHUNK) {
        __syncthreads();
        // weights: WF[ci0*9 .. +71][dt*64 .. +63]
        for (int e = tid; e < 72 * 16; e += 128) {
            int kk = e >> 4, q = e & 15;
            ((float4*)wS)[kk * 16 + q] =
                *(const float4*)(g_WF + (size_t)(ci0 * 9 + kk) * 256 + dt * 64 + q * 4);
        }
        // input: 8 ci x 9 rows x 41 cols, parity-split store
        for (int e = tid; e < CI_CHUNK * 9 * 41; e += 128) {
            int ci  = e / (9 * 41);
            int rem = e - ci * (9 * 41);
            int rr  = rem / 41;
            int c   = rem - rr * 41;
            float v = src[(size_t)(ci0 + ci) * (HH * WW) + (2 * r0 + rr) * WW + c];
            float* row = xS + (ci * 9 + rr) * XROW;
            if ((c & 1) == 0) {
                row[EAOF + (c >> 1)] = v;
                if (c >= 2) row[EBOF + (c >> 1) - 1] = v;
            } else {
                row[ODOF + (c >> 1)] = v;
            }
        }
        __syncthreads();

#pragma unroll 1
        for (int ci = 0; ci < CI_CHUNK; ci++) {
            const float* xb = xS + ci * 9 * XROW;
            const float* wb = wS + ci * 9 * 64 + dg * 4;
#pragma unroll
            for (int t = 0; t < 9; t++) {
                const int kh = t / 3, kw = t % 3;
                const int bo = (kw == 0) ? EAOF : (kw == 1) ? ODOF : EBOF;
                float4 w4 = *(const float4*)(wb + t * 64);
                ull w2[4];
                w2[0] = pack2(w4.x, w4.x); w2[1] = pack2(w4.y, w4.y);
                w2[2] = pack2(w4.z, w4.z); w2[3] = pack2(w4.w, w4.w);
                const float* xr = xb + (2 * r_loc + kh) * XROW + bo + 2 * pb;
                ull x2[5];
#pragma unroll
                for (int j = 0; j < 5; j++) x2[j] = *(const ull*)(xr + 2 * j);
#pragma unroll
                for (int i = 0; i < 4; i++)
#pragma unroll
                    for (int j = 0; j < 5; j++) ffma2(acc[i][j], w2[i], x2[j]);
            }
        }
    }

    // store: feats[img][dt*64+dg*4+i][(r0+r_loc)*20 + 2*(pb+j) .. +1]
    float* outp = g_feats + (size_t)img * FSTRIDE
                + (size_t)(dt * 64 + dg * 4) * NPOS + (r0 + r_loc) * OHW + 2 * pb;
#pragma unroll
    for (int i = 0; i < 4; i++)
#pragma unroll
        for (int j = 0; j < 5; j++)
            *(ull*)(outp + (size_t)i * NPOS + 2 * j) = acc[i][j];
}

// ---------------- 3) sim GEMM (TN): C[m][j] = scale * sum_d Q[d][m] K[d][j] ----
// grid (7 m-tiles, 16 j-tiles, 40 bk), block 256, tile 64m x 128j, K=128.
__global__ void __launch_bounds__(256) gemm1_kernel()
{
    __shared__ __align__(16) float As[16 * 64];
    __shared__ __align__(16) float Bs[16 * 128];

    const int m0 = blockIdx.x * 64;
    const int j0 = blockIdx.y * 128;
    const int bk = blockIdx.z;
    const int b  = bk / 5;
    const size_t imgbase = (size_t)(8 + bk * 5) * FSTRIDE;
    const float scale = 0.08838834764831845f;   // 128^-0.5

    const int tid = threadIdx.x;
    const int tm = (tid >> 4) * 4;
    const int tj = (tid & 15) * 8;

    ull acc[4][4];
#pragma unroll
    for (int i = 0; i < 4; i++)
#pragma unroll
        for (int p = 0; p < 4; p++) acc[i][p] = 0ULL;

    for (int d0 = 0; d0 < 128; d0 += 16) {
        __syncthreads();
        for (int e = tid; e < 16 * 64; e += 256) {
            int dd = e >> 6, mm = e & 63;
            int m = m0 + mm;
            As[e] = (m < NPOS)
                  ? scale * g_feats[(size_t)b * FSTRIDE + (size_t)(d0 + dd) * NPOS + m]
                  : 0.f;
        }
        for (int e = tid; e < 16 * 128; e += 256) {
            int dd = e >> 7, jj = e & 127;
            int j = j0 + jj;
            float v = 0.f;
            if (j < NKEY) {
                int n = j / NPOS, jp = j - n * NPOS;
                v = g_feats[imgbase + (size_t)n * FSTRIDE + (size_t)(d0 + dd) * NPOS + jp];
            }
            Bs[e] = v;
        }
        __syncthreads();

#pragma unroll
        for (int dd = 0; dd < 16; dd++) {
            float4 a4 = *(const float4*)(As + dd * 64 + tm);
            ull a2[4];
            a2[0] = pack2(a4.x, a4.x); a2[1] = pack2(a4.y, a4.y);
            a2[2] = pack2(a4.z, a4.z); a2[3] = pack2(a4.w, a4.w);
            ull b2[4];
#pragma unroll
            for (int p = 0; p < 4; p++) b2[p] = *(const ull*)(Bs + dd * 128 + tj + 2 * p);
#pragma unroll
            for (int i = 0; i < 4; i++)
#pragma unroll
                for (int p = 0; p < 4; p++) ffma2(acc[i][p], a2[i], b2[p]);
        }
    }

#pragma unroll
    for (int i = 0; i < 4; i++) {
        int m = m0 + tm + i;
        if (m < NPOS) {
            float* cp = g_sim + (size_t)bk * (NPOS * NKEY) + (size_t)m * NKEY;
#pragma unroll
            for (int p = 0; p < 4; p++) {
                int j = j0 + tj + 2 * p;
                if (j < NKEY) *(ull*)(cp + j) = acc[i][p];
            }
        }
    }
}

// ---------------- 4) row softmax over 2000 ----------------
__global__ void __launch_bounds__(256) softmax_kernel()
{
    __shared__ float sred[8];
    const int row = blockIdx.x;               // 0..15999
    float* p = g_sim + (size_t)row * NKEY;
    const int tid = threadIdx.x;

    float v[8];
    float mx = -1e30f;
#pragma unroll
    for (int i = 0; i < 8; i++) {
        int idx = tid + i * 256;
        v[i] = (idx < NKEY) ? p[idx] : -1e30f;
        mx = fmaxf(mx, v[i]);
    }
#pragma unroll
    for (int o = 16; o > 0; o >>= 1) mx = fmaxf(mx, __shfl_xor_sync(0xffffffffu, mx, o));
    if ((tid & 31) == 0) sred[tid >> 5] = mx;
    __syncthreads();
    float m0 = sred[0];
#pragma unroll
    for (int i = 1; i < 8; i++) m0 = fmaxf(m0, sred[i]);
    __syncthreads();

    float s = 0.f;
#pragma unroll
    for (int i = 0; i < 8; i++) {
        int idx = tid + i * 256;
        float e = (idx < NKEY) ? __expf(v[i] - m0) : 0.f;
        v[i] = e;
        s += e;
    }
#pragma unroll
    for (int o = 16; o > 0; o >>= 1) s += __shfl_xor_sync(0xffffffffu, s, o);
    if ((tid & 31) == 0) sred[tid >> 5] = s;
    __syncthreads();
    float tot = 0.f;
#pragma unroll
    for (int i = 0; i < 8; i++) tot += sred[i];
    float inv = 1.0f / tot;

#pragma unroll
    for (int i = 0; i < 8; i++) {
        int idx = tid + i * 256;
        if (idx < NKEY) p[idx] = v[i] * inv;
    }
}

// ---------------- 5) out GEMM (NT): Ot[c][m] = sum_kk V[c][kk] attn[m][kk] ----
// grid (4 m-tiles(128), 2 c-tiles(64), 40 bk), block 256, K chunks of 16.
__global__ void __launch_bounds__(256) gemm2_kernel()
{
    __shared__ __align__(16) float As[16 * 68];    // [kx][cc], padded stride 68
    __shared__ __align__(16) float Bs[16 * 132];   // [kx][mm], padded stride 132

    const int m0 = blockIdx.x * 128;
    const int c0 = blockIdx.y * 64;
    const int bk = blockIdx.z;
    const size_t imgbase = (size_t)(8 + bk * 5) * FSTRIDE;
    const float* attn = g_sim + (size_t)bk * (NPOS * NKEY);

    const int tid = threadIdx.x;
    const int tc = (tid >> 4) * 4;
    const int tm = (tid & 15) * 8;

    ull acc[4][4];
#pragma unroll
    for (int i = 0; i < 4; i++)
#pragma unroll
        for (int p = 0; p < 4; p++) acc[i][p] = 0ULL;

    for (int k0 = 0; k0 < NKEY; k0 += 16) {
        __syncthreads();
        {   // V tile: feats[img(n)][128+c][jp]; chunk never crosses an n boundary
            int n = k0 / NPOS, jp0 = k0 - n * NPOS;
            const float* vsrc = g_feats + imgbase + (size_t)n * FSTRIDE
                              + (size_t)(128 + c0) * NPOS + jp0;
            for (int e = tid; e < 64 * 16; e += 256) {
                int cc = e >> 4, kx = e & 15;
                As[kx * 68 + cc] = vsrc[(size_t)cc * NPOS + kx];
            }
        }
        for (int e = tid; e < 128 * 16; e += 256) {
            int mm = e >> 4, kx = e & 15;
            int m = m0 + mm;
            Bs[kx * 132 + mm] = (m < NPOS) ? attn[(size_t)m * NKEY + k0 + kx] : 0.f;
        }
        __syncthreads();

#pragma unroll
        for (int kx = 0; kx < 16; kx++) {
            float4 a4 = *(const float4*)(As + kx * 68 + tc);
            ull a2[4];
            a2[0] = pack2(a4.x, a4.x); a2[1] = pack2(a4.y, a4.y);
            a2[2] = pack2(a4.z, a4.z); a2[3] = pack2(a4.w, a4.w);
            ull b2[4];
#pragma unroll
            for (int p = 0; p < 4; p++) b2[p] = *(const ull*)(Bs + kx * 132 + tm + 2 * p);
#pragma unroll
            for (int i = 0; i < 4; i++)
#pragma unroll
                for (int p = 0; p < 4; p++) ffma2(acc[i][p], a2[i], b2[p]);
        }
    }

#pragma unroll
    for (int i = 0; i < 4; i++) {
        float* op = g_Ot + (size_t)bk * (128 * NPOS) + (size_t)(c0 + tc + i) * NPOS;
#pragma unroll
        for (int p = 0; p < 4; p++) {
            int m = m0 + tm + 2 * p;
            if (m < NPOS) *(ull*)(op + m) = acc[i][p];
        }
    }
}

// ---------------- 6) distance reduce ----------------
__global__ void __launch_bounds__(256) dist_kernel(float* __restrict__ out)
{
    __shared__ float sred[8];
    const int bk = blockIdx.x;
    const int b  = bk / 5;
    const float* qv = g_feats + (size_t)b * FSTRIDE + (size_t)128 * NPOS;
    const float* o  = g_Ot + (size_t)bk * (128 * NPOS);
    const int tid = threadIdx.x;

    float s = 0.f;
    for (int e = tid; e < 128 * NPOS; e += 256) {
        float d = qv[e] - o[e];
        s += d * d;
    }
#pragma unroll
    for (int off = 16; off > 0; off >>= 1) s += __shfl_xor_sync(0xffffffffu, s, off);
    if ((tid & 31) == 0) sred[tid >> 5] = s;
    __syncthreads();
    if (tid == 0) {
        float tot = 0.f;
#pragma unroll
        for (int i = 0; i < 8; i++) tot += sred[i];
        out[bk] = -tot * (1.0f / 400.0f);
    }
}

// ---------------------------------------------------------------------------
extern "C" void kernel_launch(void* const* d_in, const int* in_sizes, int n_in,
                              void* d_out, int out_size)
{
    const float* img_query    = (const float*)d_in[0];
    const float* img_supports = (const float*)d_in[1];
    const float* w_qk         = (const float*)d_in[2];
    const float* w_v          = (const float*)d_in[3];
    const float* w_ms         = (const float*)d_in[4];
    float* out = (float*)d_out;

    fuse_kernel<<<288, 256>>>(w_qk, w_v, w_ms);
    conv_kernel<<<dim3(5, 4, 208), 128>>>(img_query, img_supports);
    gemm1_kernel<<<dim3(7, 16, 40), 256>>>();
    softmax_kernel<<<16000, 256>>>();
    gemm2_kernel<<<dim3(4, 2, 40), 256>>>();
    dist_kernel<<<40, 256>>>(out);
}

// round 11
// speedup vs baseline: 1.3936x; 1.3936x over previous
#include <cuda_runtime.h>
#include <cuda_bf16.h>
#include <cstdint>

// ---------------------------------------------------------------------------
// MultiCrossTransformer on GB300 (sm_103a board, compute_103 virtual arch:
// NO tcgen05 — base-ISA mma.sync bf16 tensor path instead).
//
//  1) fuse_kernel : W[d][k] = sum_c proj[d][c]*w_ms[c][k], emitted bf16 hi/lo
//  2) conv_mma    : feats[img][d][400] = conv3x3_s2 via mma.sync implicit GEMM
//                   (bf16 3-term split: Wh*Xh + Wh*Xl + Wl*Xh, fp32 accum)
//  3) gemm1       : sim = scale * Q^T K        (f32x2 scalar)
//  4) softmax     : row softmax over 2000
//  5) gemm2       : Ot = V attn^T              (f32x2 scalar)
//  6) dist        : out[bk] = -||qv - Ot||^2 / 400
// ---------------------------------------------------------------------------

typedef unsigned long long ull;

#define IC    512
#define HH    41
#define WW    41
#define OHW   20
#define NPOS  400
#define NIMG  208
#define FSTRIDE 102400      // 256*400 floats per image
#define NKEY  2000
#define NBK   40
#define KTOT  4608          // 512*9

// scratch (device globals; no allocation APIs)
__device__ __nv_bfloat16 g_Whi[(size_t)256 * KTOT];   // [d][k]
__device__ __nv_bfloat16 g_Wlo[(size_t)256 * KTOT];
__device__ float g_feats[(size_t)NIMG * 256 * NPOS];
__device__ float g_sim[(size_t)NBK * NPOS * NKEY];
__device__ float g_Ot[(size_t)NBK * 128 * NPOS];

// ---------------- f32x2 helpers (scalar GEMMs) ----------------
__device__ __forceinline__ void ffma2(ull& d, ull a, ull b) {
    asm("fma.rn.f32x2 %0, %1, %2, %0;" : "+l"(d) : "l"(a), "l"(b));
}
__device__ __forceinline__ ull pack2(float x, float y) {
    ull r; asm("mov.b64 %0, {%1, %2};" : "=l"(r) : "f"(x), "f"(y)); return r;
}

// ---------------- mma.sync / ldmatrix helpers (base ISA) ----------------
__device__ __forceinline__ uint32_t smem_u32(const void* p) {
    uint32_t a;
    asm("{ .reg .u64 t; cvta.to.shared.u64 t, %1; cvt.u32.u64 %0, t; }" : "=r"(a) : "l"(p));
    return a;
}
__device__ __forceinline__ void ldsm4(uint32_t* r, uint32_t a) {
    asm volatile("ldmatrix.sync.aligned.m8n8.x4.shared.b16 {%0,%1,%2,%3}, [%4];"
        : "=r"(r[0]), "=r"(r[1]), "=r"(r[2]), "=r"(r[3]) : "r"(a));
}
__device__ __forceinline__ void mma16816(float* d, const uint32_t* a, const uint32_t* b) {
    asm volatile(
        "mma.sync.aligned.m16n8k16.row.col.f32.bf16.bf16.f32 "
        "{%0,%1,%2,%3}, {%4,%5,%6,%7}, {%8,%9}, {%0,%1,%2,%3};"
        : "+f"(d[0]), "+f"(d[1]), "+f"(d[2]), "+f"(d[3])
        : "r"(a[0]), "r"(a[1]), "r"(a[2]), "r"(a[3]), "r"(b[0]), "r"(b[1]));
}

// ---------------- 1) weight fusion -> bf16 hi/lo, [d][k] layout ----------------
__global__ void __launch_bounds__(256) fuse_kernel(
    const float* __restrict__ w_qk, const float* __restrict__ w_v,
    const float* __restrict__ w_ms)
{
    __shared__ __align__(16) float wcol[512 * 16];   // [c][t]
    int k0 = blockIdx.x * 16;
    int d  = threadIdx.x;

    for (int e = d; e < 512 * 16; e += 256) {
        int c = e >> 4, t = e & 15;
        wcol[e] = w_ms[(size_t)c * KTOT + k0 + t];
    }
    __syncthreads();

    const float4* proj4 = (const float4*)((d < 128) ? (w_qk + (size_t)d * 512)
                                                    : (w_v  + (size_t)(d - 128) * 512));
    float acc[16];
#pragma unroll
    for (int t = 0; t < 16; t++) acc[t] = 0.f;

    for (int c4 = 0; c4 < 128; c4++) {
        float4 p = proj4[c4];
#pragma unroll
        for (int q = 0; q < 4; q++) {
            float pv = (q == 0) ? p.x : (q == 1) ? p.y : (q == 2) ? p.z : p.w;
            const float4* wf = (const float4*)(wcol + (c4 * 4 + q) * 16);
            float4 b0 = wf[0], b1 = wf[1], b2 = wf[2], b3 = wf[3];
            acc[0]  += pv * b0.x;  acc[1]  += pv * b0.y;
            acc[2]  += pv * b0.z;  acc[3]  += pv * b0.w;
            acc[4]  += pv * b1.x;  acc[5]  += pv * b1.y;
            acc[6]  += pv * b1.z;  acc[7]  += pv * b1.w;
            acc[8]  += pv * b2.x;  acc[9]  += pv * b2.y;
            acc[10] += pv * b2.z;  acc[11] += pv * b2.w;
            acc[12] += pv * b3.x;  acc[13] += pv * b3.y;
            acc[14] += pv * b3.z;  acc[15] += pv * b3.w;
        }
    }
#pragma unroll
    for (int t = 0; t < 16; t++) {
        float a = acc[t];
        __nv_bfloat16 h = __float2bfloat16(a);
        __nv_bfloat16 l = __float2bfloat16(a - __bfloat162float(h));
        g_Whi[(size_t)d * KTOT + k0 + t] = h;
        g_Wlo[(size_t)d * KTOT + k0 + t] = l;
    }
}

// ---------------- 2) conv via mma.sync bf16-split implicit GEMM ----------------
// C[p][d] = sum_k X[p][k] * W[k][d];   A = im2col X (row), B = W[d][k] (col).
// CTA tile: 128 pos x 128 d, 8 warps (2x4), warp tile 64 x 32.
// K = 4608 in 144 chunks of 32, 3-stage SMEM ring.
// SMEM rows: 128B = [32 bf16 hi | 32 bf16 lo], SW128 swizzle.
#define NCH   144
#define STG   32768
#define XOFF  0
#define WOFF  16384

struct CvPref {
    float x0[8], x1[8];
    uint4 wh[2], wl[2];
};

__device__ __forceinline__ void cv_load(
    CvPref& P, const float* __restrict__ src,
    const __nv_bfloat16* __restrict__ whB, const __nv_bfloat16* __restrict__ wlB,
    int c, int tid, int pbase)
{
#pragma unroll
    for (int i = 0; i < 8; i++) {
        int e   = i * 256 + tid;
        int kk2 = e >> 7, mp = e & 127;
        int p   = pbase + mp;
        float x0 = 0.f, x1 = 0.f;
        if (p < NPOS) {
            int r  = (p * 205) >> 12;        // p / 20
            int cc = p - r * 20;
            int k  = c * 32 + kk2 * 2;
            int ci = k / 9, t = k - ci * 9;
            const float* bp = src + (size_t)ci * 1681 + (2 * r) * 41 + 2 * cc;
            x0 = bp[(t / 3) * 41 + (t % 3)];
            int t1 = t + 1;
            const float* bp1 = bp;
            if (t1 == 9) { t1 = 0; bp1 += 1681; }
            x1 = bp1[(t1 / 3) * 41 + (t1 % 3)];
        }
        P.x0[i] = x0; P.x1[i] = x1;
    }
#pragma unroll
    for (int i = 0; i < 2; i++) {
        int e = i * 256 + tid;
        int d = e >> 2, seg = e & 3;
        P.wh[i] = *(const uint4*)(whB + (size_t)d * KTOT + c * 32 + seg * 8);
        P.wl[i] = *(const uint4*)(wlB + (size_t)d * KTOT + c * 32 + seg * 8);
    }
}

__device__ __forceinline__ void cv_store(const CvPref& P, char* stage, int tid)
{
#pragma unroll
    for (int i = 0; i < 8; i++) {
        int e   = i * 256 + tid;
        int kk2 = e >> 7, mp = e & 127;
        __nv_bfloat16 h0 = __float2bfloat16(P.x0[i]);
        __nv_bfloat16 l0 = __float2bfloat16(P.x0[i] - __bfloat162float(h0));
        __nv_bfloat16 h1 = __float2bfloat16(P.x1[i]);
        __nv_bfloat16 l1 = __float2bfloat16(P.x1[i] - __bfloat162float(h1));
        uint32_t hp = (uint32_t)__bfloat16_as_ushort(h0) | ((uint32_t)__bfloat16_as_ushort(h1) << 16);
        uint32_t lp = (uint32_t)__bfloat16_as_ushort(l0) | ((uint32_t)__bfloat16_as_ushort(l1) << 16);
        uint32_t xr = (uint32_t)(mp & 7) * 16u;
        char* row = stage + XOFF + (uint32_t)mp * 128u;
        *(uint32_t*)(row + ((kk2 * 4)      ^ xr)) = hp;
        *(uint32_t*)(row + ((64 + kk2 * 4) ^ xr)) = lp;
    }
#pragma unroll
    for (int i = 0; i < 2; i++) {
        int e = i * 256 + tid;
        int d = e >> 2, seg = e & 3;
        uint32_t xr = (uint32_t)(d & 7) * 16u;
        char* row = stage + WOFF + (uint32_t)d * 128u;
        *(uint4*)(row + ((seg * 16)      ^ xr)) = P.wh[i];
        *(uint4*)(row + ((64 + seg * 16) ^ xr)) = P.wl[i];
    }
}

__global__ void __launch_bounds__(256) conv_mma_kernel(
    const float* __restrict__ img_query, const float* __restrict__ img_supports)
{
    extern __shared__ __align__(128) char smem[];
    const int tid = threadIdx.x;
    const int l   = tid & 31, w = tid >> 5;
    const int pt  = blockIdx.x;                 // 0..3 (pos tiles of 128)
    const int dt  = blockIdx.y;                 // 0..1 (d tiles of 128)
    const int img = blockIdx.z;                 // 0..207
    const float* src = (img < 8) ? (img_query + (size_t)img * IC * HH * WW)
                                 : (img_supports + (size_t)(img - 8) * IC * HH * WW);
    const int pbase = pt * 128;
    const int wm = (w >> 2) * 64;               // warp pos offset
    const int wn = (w & 3) * 32;                // warp d offset
    const __nv_bfloat16* whB = g_Whi + (size_t)(dt * 128) * KTOT;
    const __nv_bfloat16* wlB = g_Wlo + (size_t)(dt * 128) * KTOT;
    const uint32_t sbase = smem_u32(smem);

    // per-lane ldmatrix row offsets (bytes) + swizzle xor
    uint32_t arow[4], axor[4], brow[2], bxor[2];
#pragma unroll
    for (int mi = 0; mi < 4; mi++) {
        int r = wm + mi * 16 + (l & 15);
        arow[mi] = (uint32_t)r * 128u;
        axor[mi] = (uint32_t)(r & 7) * 16u;
    }
#pragma unroll
    for (int ni2 = 0; ni2 < 2; ni2++) {
        int r = wn + ni2 * 16 + (l & 7) + ((l >> 4) << 3);
        brow[ni2] = (uint32_t)r * 128u;
        bxor[ni2] = (uint32_t)(r & 7) * 16u;
    }

    float acc[4][4][4];
#pragma unroll
    for (int mi = 0; mi < 4; mi++)
#pragma unroll
        for (int ni = 0; ni < 4; ni++)
#pragma unroll
            for (int q = 0; q < 4; q++) acc[mi][ni][q] = 0.f;

    CvPref P;
    cv_load(P, src, whB, wlB, 0, tid, pbase);  cv_store(P, smem + 0 * STG, tid);
    cv_load(P, src, whB, wlB, 1, tid, pbase);  cv_store(P, smem + 1 * STG, tid);

    int sidx = 0;
    for (int c = 0; c < NCH; c++) {
        __syncthreads();
        const bool pf = (c + 2 < NCH);
        if (pf) cv_load(P, src, whB, wlB, c + 2, tid, pbase);

        const uint32_t sX = sbase + (uint32_t)sidx * STG + XOFF;
        const uint32_t sW = sbase + (uint32_t)sidx * STG + WOFF;
        const uint32_t ca0 = (uint32_t)((l >> 4) << 4);
        const uint32_t cb0 = (uint32_t)(((l >> 3) & 1) << 4);

#pragma unroll
        for (int ks = 0; ks < 2; ks++) {
            const uint32_t colA = (uint32_t)(ks * 32) + ca0;
            const uint32_t colB = (uint32_t)(ks * 32) + cb0;
            uint32_t Ah[4][4], Bf[4][2], t4[4];

            // A hi
#pragma unroll
            for (int mi = 0; mi < 4; mi++)
                ldsm4(Ah[mi], sX + arow[mi] + (colA ^ axor[mi]));
            // B hi
#pragma unroll
            for (int ni2 = 0; ni2 < 2; ni2++) {
                ldsm4(t4, sW + brow[ni2] + (colB ^ bxor[ni2]));
                Bf[ni2 * 2][0] = t4[0]; Bf[ni2 * 2][1] = t4[1];
                Bf[ni2 * 2 + 1][0] = t4[2]; Bf[ni2 * 2 + 1][1] = t4[3];
            }
#pragma unroll
            for (int mi = 0; mi < 4; mi++)
#pragma unroll
                for (int ni = 0; ni < 4; ni++)
                    mma16816(acc[mi][ni], Ah[mi], Bf[ni]);

            // B lo (overwrite Bh)
#pragma unroll
            for (int ni2 = 0; ni2 < 2; ni2++) {
                ldsm4(t4, sW + brow[ni2] + ((colB + 64) ^ bxor[ni2]));
                Bf[ni2 * 2][0] = t4[0]; Bf[ni2 * 2][1] = t4[1];
                Bf[ni2 * 2 + 1][0] = t4[2]; Bf[ni2 * 2 + 1][1] = t4[3];
            }
#pragma unroll
            for (int mi = 0; mi < 4; mi++)
#pragma unroll
                for (int ni = 0; ni < 4; ni++)
                    mma16816(acc[mi][ni], Ah[mi], Bf[ni]);

            // A lo (overwrite Ah), B hi reload
#pragma unroll
            for (int mi = 0; mi < 4; mi++)
                ldsm4(Ah[mi], sX + arow[mi] + ((colA + 64) ^ axor[mi]));
#pragma unroll
            for (int ni2 = 0; ni2 < 2; ni2++) {
                ldsm4(t4, sW + brow[ni2] + (colB ^ bxor[ni2]));
                Bf[ni2 * 2][0] = t4[0]; Bf[ni2 * 2][1] = t4[1];
                Bf[ni2 * 2 + 1][0] = t4[2]; Bf[ni2 * 2 + 1][1] = t4[3];
            }
#pragma unroll
            for (int mi = 0; mi < 4; mi++)
#pragma unroll
                for (int ni = 0; ni < 4; ni++)
                    mma16816(acc[mi][ni], Ah[mi], Bf[ni]);
        }

        if (pf) cv_store(P, smem + (size_t)((sidx + 2) % 3) * STG, tid);
        sidx++; if (sidx == 3) sidx = 0;
    }

    // epilogue: C frag (p0=l/4, d0=2*(l%4)) -> feats[img][d][p]
    const int prow = pbase + wm + (l >> 2);
    const int dcol = dt * 128 + wn + 2 * (l & 3);
    float* fb = g_feats + (size_t)img * FSTRIDE;
#pragma unroll
    for (int mi = 0; mi < 4; mi++) {
        int p0 = prow + mi * 16;
#pragma unroll
        for (int ni = 0; ni < 4; ni++) {
            int d0 = dcol + ni * 8;
            if (p0 < NPOS) {
                fb[(size_t)d0 * NPOS + p0]       = acc[mi][ni][0];
                fb[(size_t)(d0 + 1) * NPOS + p0] = acc[mi][ni][1];
            }
            if (p0 + 8 < NPOS) {
                fb[(size_t)d0 * NPOS + p0 + 8]       = acc[mi][ni][2];
                fb[(size_t)(d0 + 1) * NPOS + p0 + 8] = acc[mi][ni][3];
            }
        }
    }
}

// ---------------- 3) sim GEMM (TN): C[m][j] = scale * sum_d Q[d][m] K[d][j] ----
__global__ void __launch_bounds__(256) gemm1_kernel()
{
    __shared__ __align__(16) float As[16 * 64];
    __shared__ __align__(16) float Bs[16 * 128];

    const int m0 = blockIdx.x * 64;
    const int j0 = blockIdx.y * 128;
    const int bk = blockIdx.z;
    const int b  = bk / 5;
    const size_t imgbase = (size_t)(8 + bk * 5) * FSTRIDE;
    const float scale = 0.08838834764831845f;   // 128^-0.5

    const int tid = threadIdx.x;
    const int tm = (tid >> 4) * 4;
    const int tj = (tid & 15) * 8;

    ull acc[4][4];
#pragma unroll
    for (int i = 0; i < 4; i++)
#pragma unroll
        for (int p = 0; p < 4; p++) acc[i][p] = 0ULL;

    for (int d0 = 0; d0 < 128; d0 += 16) {
        __syncthreads();
        for (int e = tid; e < 16 * 64; e += 256) {
            int dd = e >> 6, mm = e & 63;
            int m = m0 + mm;
            As[e] = (m < NPOS)
                  ? scale * g_feats[(size_t)b * FSTRIDE + (size_t)(d0 + dd) * NPOS + m]
                  : 0.f;
        }
        for (int e = tid; e < 16 * 128; e += 256) {
            int dd = e >> 7, jj = e & 127;
            int j = j0 + jj;
            float v = 0.f;
            if (j < NKEY) {
                int n = j / NPOS, jp = j - n * NPOS;
                v = g_feats[imgbase + (size_t)n * FSTRIDE + (size_t)(d0 + dd) * NPOS + jp];
            }
            Bs[e] = v;
        }
        __syncthreads();

#pragma unroll
        for (int dd = 0; dd < 16; dd++) {
            float4 a4 = *(const float4*)(As + dd * 64 + tm);
            ull a2[4];
            a2[0] = pack2(a4.x, a4.x); a2[1] = pack2(a4.y, a4.y);
            a2[2] = pack2(a4.z, a4.z); a2[3] = pack2(a4.w, a4.w);
            ull b2[4];
#pragma unroll
            for (int p = 0; p < 4; p++) b2[p] = *(const ull*)(Bs + dd * 128 + tj + 2 * p);
#pragma unroll
            for (int i = 0; i < 4; i++)
#pragma unroll
                for (int p = 0; p < 4; p++) ffma2(acc[i][p], a2[i], b2[p]);
        }
    }

#pragma unroll
    for (int i = 0; i < 4; i++) {
        int m = m0 + tm + i;
        if (m < NPOS) {
            float* cp = g_sim + (size_t)bk * (NPOS * NKEY) + (size_t)m * NKEY;
#pragma unroll
            for (int p = 0; p < 4; p++) {
                int j = j0 + tj + 2 * p;
                if (j < NKEY) *(ull*)(cp + j) = acc[i][p];
            }
        }
    }
}

// ---------------- 4) row softmax over 2000 ----------------
__global__ void __launch_bounds__(256) softmax_kernel()
{
    __shared__ float sred[8];
    const int row = blockIdx.x;
    float* p = g_sim + (size_t)row * NKEY;
    const int tid = threadIdx.x;

    float v[8];
    float mx = -1e30f;
#pragma unroll
    for (int i = 0; i < 8; i++) {
        int idx = tid + i * 256;
        v[i] = (idx < NKEY) ? p[idx] : -1e30f;
        mx = fmaxf(mx, v[i]);
    }
#pragma unroll
    for (int o = 16; o > 0; o >>= 1) mx = fmaxf(mx, __shfl_xor_sync(0xffffffffu, mx, o));
    if ((tid & 31) == 0) sred[tid >> 5] = mx;
    __syncthreads();
    float m0 = sred[0];
#pragma unroll
    for (int i = 1; i < 8; i++) m0 = fmaxf(m0, sred[i]);
    __syncthreads();

    float s = 0.f;
#pragma unroll
    for (int i = 0; i < 8; i++) {
        int idx = tid + i * 256;
        float e = (idx < NKEY) ? __expf(v[i] - m0) : 0.f;
        v[i] = e;
        s += e;
    }
#pragma unroll
    for (int o = 16; o > 0; o >>= 1) s += __shfl_xor_sync(0xffffffffu, s, o);
    if ((tid & 31) == 0) sred[tid >> 5] = s;
    __syncthreads();
    float tot = 0.f;
#pragma unroll
    for (int i = 0; i < 8; i++) tot += sred[i];
    float inv = 1.0f / tot;

#pragma unroll
    for (int i = 0; i < 8; i++) {
        int idx = tid + i * 256;
        if (idx < NKEY) p[idx] = v[i] * inv;
    }
}

// ---------------- 5) out GEMM (NT): Ot[c][m] = sum_kk V[c][kk] attn[m][kk] ----
__global__ void __launch_bounds__(256) gemm2_kernel()
{
    __shared__ __align__(16) float As[16 * 68];
    __shared__ __align__(16) float Bs[16 * 132];

    const int m0 = blockIdx.x * 128;
    const int c0 = blockIdx.y * 64;
    const int bk = blockIdx.z;
    const size_t imgbase = (size_t)(8 + bk * 5) * FSTRIDE;
    const float* attn = g_sim + (size_t)bk * (NPOS * NKEY);

    const int tid = threadIdx.x;
    const int tc = (tid >> 4) * 4;
    const int tm = (tid & 15) * 8;

    ull acc[4][4];
#pragma unroll
    for (int i = 0; i < 4; i++)
#pragma unroll
        for (int p = 0; p < 4; p++) acc[i][p] = 0ULL;

    for (int k0 = 0; k0 < NKEY; k0 += 16) {
        __syncthreads();
        {
            int n = k0 / NPOS, jp0 = k0 - n * NPOS;
            const float* vsrc = g_feats + imgbase + (size_t)n * FSTRIDE
                              + (size_t)(128 + c0) * NPOS + jp0;
            for (int e = tid; e < 64 * 16; e += 256) {
                int cc = e >> 4, kx = e & 15;
                As[kx * 68 + cc] = vsrc[(size_t)cc * NPOS + kx];
            }
        }
        for (int e = tid; e < 128 * 16; e += 256) {
            int mm = e >> 4, kx = e & 15;
            int m = m0 + mm;
            Bs[kx * 132 + mm] = (m < NPOS) ? attn[(size_t)m * NKEY + k0 + kx] : 0.f;
        }
        __syncthreads();

#pragma unroll
        for (int kx = 0; kx < 16; kx++) {
            float4 a4 = *(const float4*)(As + kx * 68 + tc);
            ull a2[4];
            a2[0] = pack2(a4.x, a4.x); a2[1] = pack2(a4.y, a4.y);
            a2[2] = pack2(a4.z, a4.z); a2[3] = pack2(a4.w, a4.w);
            ull b2[4];
#pragma unroll
            for (int p = 0; p < 4; p++) b2[p] = *(const ull*)(Bs + kx * 132 + tm + 2 * p);
#pragma unroll
            for (int i = 0; i < 4; i++)
#pragma unroll
                for (int p = 0; p < 4; p++) ffma2(acc[i][p], a2[i], b2[p]);
        }
    }

#pragma unroll
    for (int i = 0; i < 4; i++) {
        float* op = g_Ot + (size_t)bk * (128 * NPOS) + (size_t)(c0 + tc + i) * NPOS;
#pragma unroll
        for (int p = 0; p < 4; p++) {
            int m = m0 + tm + 2 * p;
            if (m < NPOS) *(ull*)(op + m) = acc[i][p];
        }
    }
}

// ---------------- 6) distance reduce ----------------
__global__ void __launch_bounds__(256) dist_kernel(float* __restrict__ out)
{
    __shared__ float sred[8];
    const int bk = blockIdx.x;
    const int b  = bk / 5;
    const float* qv = g_feats + (size_t)b * FSTRIDE + (size_t)128 * NPOS;
    const float* o  = g_Ot + (size_t)bk * (128 * NPOS);
    const int tid = threadIdx.x;

    float s = 0.f;
    for (int e = tid; e < 128 * NPOS; e += 256) {
        float d = qv[e] - o[e];
        s += d * d;
    }
#pragma unroll
    for (int off = 16; off > 0; off >>= 1) s += __shfl_xor_sync(0xffffffffu, s, off);
    if ((tid & 31) == 0) sred[tid >> 5] = s;
    __syncthreads();
    if (tid == 0) {
        float tot = 0.f;
#pragma unroll
        for (int i = 0; i < 8; i++) tot += sred[i];
        out[bk] = -tot * (1.0f / 400.0f);
    }
}

// ---------------------------------------------------------------------------
extern "C" void kernel_launch(void* const* d_in, const int* in_sizes, int n_in,
                              void* d_out, int out_size)
{
    const float* img_query    = (const float*)d_in[0];
    const float* img_supports = (const float*)d_in[1];
    const float* w_qk         = (const float*)d_in[2];
    const float* w_v          = (const float*)d_in[3];
    const float* w_ms         = (const float*)d_in[4];
    float* out = (float*)d_out;

    static bool attr_set = false;
    if (!attr_set) {
        cudaFuncSetAttribute(conv_mma_kernel,
                             cudaFuncAttributeMaxDynamicSharedMemorySize, 3 * STG);
        attr_set = true;
    }

    fuse_kernel<<<288, 256>>>(w_qk, w_v, w_ms);
    conv_mma_kernel<<<dim3(4, 2, NIMG), 256, 3 * STG>>>(img_query, img_supports);
    gemm1_kernel<<<dim3(7, 16, 40), 256>>>();
    softmax_kernel<<<16000, 256>>>();
    gemm2_kernel<<<dim3(4, 2, 40), 256>>>();
    dist_kernel<<<40, 256>>>(out);
}

// round 12
// speedup vs baseline: 1.7306x; 1.2418x over previous
#include <cuda_runtime.h>
#include <cuda_bf16.h>
#include <cstdint>

// ---------------------------------------------------------------------------
// MultiCrossTransformer on GB300 (sm_103a board, compute_103 virtual arch:
// NO tcgen05 — base-ISA mma.sync bf16 tensor path).
//
//  1) fuse_kernel : W[d][k] = sum_c proj[d][c]*w_ms[c][k], emitted bf16 hi/lo
//  2) conv_mma    : feats[img][d][400] = conv3x3_s2 via mma.sync implicit GEMM
//                   (bf16 3-term split: Wh*Xh + Wh*Xl + Wl*Xh, fp32 accum)
//                   512-thr CTA, 128p x 256d tile, cp.async W stream, 3-stage ring
//  3) gemm1       : sim = scale * Q^T K        (f32x2 scalar)
//  4) softmax     : row softmax over 2000
//  5) gemm2       : Ot = V attn^T              (f32x2 scalar)
//  6) dist        : out[bk] = -||qv - Ot||^2 / 400
// ---------------------------------------------------------------------------

typedef unsigned long long ull;

#define IC    512
#define HH    41
#define WW    41
#define OHW   20
#define NPOS  400
#define NIMG  208
#define FSTRIDE 102400      // 256*400 floats per image
#define NKEY  2000
#define NBK   40
#define KTOT  4608          // 512*9

// scratch (device globals; no allocation APIs)
__device__ __nv_bfloat16 g_Whi[(size_t)256 * KTOT];   // [d][k]
__device__ __nv_bfloat16 g_Wlo[(size_t)256 * KTOT];
__device__ float g_feats[(size_t)NIMG * 256 * NPOS];
__device__ float g_sim[(size_t)NBK * NPOS * NKEY];
__device__ float g_Ot[(size_t)NBK * 128 * NPOS];

// ---------------- f32x2 helpers (scalar GEMMs) ----------------
__device__ __forceinline__ void ffma2(ull& d, ull a, ull b) {
    asm("fma.rn.f32x2 %0, %1, %2, %0;" : "+l"(d) : "l"(a), "l"(b));
}
__device__ __forceinline__ ull pack2(float x, float y) {
    ull r; asm("mov.b64 %0, {%1, %2};" : "=l"(r) : "f"(x), "f"(y)); return r;
}

// ---------------- mma.sync / ldmatrix / cp.async helpers (base ISA) --------
__device__ __forceinline__ uint32_t smem_u32(const void* p) {
    uint32_t a;
    asm("{ .reg .u64 t; cvta.to.shared.u64 t, %1; cvt.u32.u64 %0, t; }" : "=r"(a) : "l"(p));
    return a;
}
__device__ __forceinline__ void ldsm4(uint32_t* r, uint32_t a) {
    asm volatile("ldmatrix.sync.aligned.m8n8.x4.shared.b16 {%0,%1,%2,%3}, [%4];"
        : "=r"(r[0]), "=r"(r[1]), "=r"(r[2]), "=r"(r[3]) : "r"(a));
}
__device__ __forceinline__ void mma16816(float* d, const uint32_t* a, const uint32_t* b) {
    asm volatile(
        "mma.sync.aligned.m16n8k16.row.col.f32.bf16.bf16.f32 "
        "{%0,%1,%2,%3}, {%4,%5,%6,%7}, {%8,%9}, {%0,%1,%2,%3};"
        : "+f"(d[0]), "+f"(d[1]), "+f"(d[2]), "+f"(d[3])
        : "r"(a[0]), "r"(a[1]), "r"(a[2]), "r"(a[3]), "r"(b[0]), "r"(b[1]));
}
__device__ __forceinline__ void cp_async16(uint32_t dst, const void* src) {
    asm volatile("cp.async.cg.shared.global [%0], [%1], 16;" :: "r"(dst), "l"(src));
}
#define CP_COMMIT() asm volatile("cp.async.commit_group;" ::: "memory")
#define CP_WAIT1()  asm volatile("cp.async.wait_group 1;" ::: "memory")

// ---------------- 1) weight fusion -> bf16 hi/lo, [d][k] layout ----------------
__global__ void __launch_bounds__(256) fuse_kernel(
    const float* __restrict__ w_qk, const float* __restrict__ w_v,
    const float* __restrict__ w_ms)
{
    __shared__ __align__(16) float wcol[512 * 16];   // [c][t]
    int k0 = blockIdx.x * 16;
    int d  = threadIdx.x;

    for (int e = d; e < 512 * 16; e += 256) {
        int c = e >> 4, t = e & 15;
        wcol[e] = w_ms[(size_t)c * KTOT + k0 + t];
    }
    __syncthreads();

    const float4* proj4 = (const float4*)((d < 128) ? (w_qk + (size_t)d * 512)
                                                    : (w_v  + (size_t)(d - 128) * 512));
    float acc[16];
#pragma unroll
    for (int t = 0; t < 16; t++) acc[t] = 0.f;

    for (int c4 = 0; c4 < 128; c4++) {
        float4 p = proj4[c4];
#pragma unroll
        for (int q = 0; q < 4; q++) {
            float pv = (q == 0) ? p.x : (q == 1) ? p.y : (q == 2) ? p.z : p.w;
            const float4* wf = (const float4*)(wcol + (c4 * 4 + q) * 16);
            float4 b0 = wf[0], b1 = wf[1], b2 = wf[2], b3 = wf[3];
            acc[0]  += pv * b0.x;  acc[1]  += pv * b0.y;
            acc[2]  += pv * b0.z;  acc[3]  += pv * b0.w;
            acc[4]  += pv * b1.x;  acc[5]  += pv * b1.y;
            acc[6]  += pv * b1.z;  acc[7]  += pv * b1.w;
            acc[8]  += pv * b2.x;  acc[9]  += pv * b2.y;
            acc[10] += pv * b2.z;  acc[11] += pv * b2.w;
            acc[12] += pv * b3.x;  acc[13] += pv * b3.y;
            acc[14] += pv * b3.z;  acc[15] += pv * b3.w;
        }
    }
#pragma unroll
    for (int t = 0; t < 16; t++) {
        float a = acc[t];
        __nv_bfloat16 h = __float2bfloat16(a);
        __nv_bfloat16 l = __float2bfloat16(a - __bfloat162float(h));
        g_Whi[(size_t)d * KTOT + k0 + t] = h;
        g_Wlo[(size_t)d * KTOT + k0 + t] = l;
    }
}

// ---------------- 2) conv via mma.sync bf16-split implicit GEMM ----------------
// C[p][d] = sum_k X[p][k] * W[k][d]; 512 threads, CTA tile 128p x 256d.
// 16 warps as 2(m) x 8(n); warp tile 64p x 32d. K = 4608 in 144 chunks of 32.
// Stage: X 128x128B rows (32 k hi | 32 k lo, swizzled) + W 256x128B rows.
#define NCH    144
#define CSTG   49152
#define CXOFF  0
#define CWOFF  16384

__device__ __forceinline__ void cv_prefx(
    float* xv, const float* __restrict__ rowbase, bool pvalid, int tS, int ciS)
{
    int tl = tS, cil = ciS;
#pragma unroll
    for (int i = 0; i < 4; i++) {
        float x0 = 0.f, x1 = 0.f;
        if (pvalid) {
            int th = (tl * 11) >> 5;
            x0 = rowbase[cil * 1681 + th * 41 + (tl - 3 * th)];
            int t1 = tl + 1, c1 = cil;
            if (t1 == 9) { t1 = 0; c1++; }
            int th1 = (t1 * 11) >> 5;
            x1 = rowbase[c1 * 1681 + th1 * 41 + (t1 - 3 * th1)];
        }
        xv[2 * i] = x0; xv[2 * i + 1] = x1;
        tl += 8; if (tl >= 9) { tl -= 9; cil++; }
    }
}

__device__ __forceinline__ void cv_stx(const float* xv, char* stage, int mp, int h2)
{
    uint32_t xr = (uint32_t)(mp & 7) * 16u;
    char* row = stage + CXOFF + (uint32_t)mp * 128u;
#pragma unroll
    for (int i = 0; i < 4; i++) {
        int kk2 = i * 4 + h2;
        float x0 = xv[2 * i], x1 = xv[2 * i + 1];
        __nv_bfloat16 h0 = __float2bfloat16(x0);
        __nv_bfloat16 l0 = __float2bfloat16(x0 - __bfloat162float(h0));
        __nv_bfloat16 h1 = __float2bfloat16(x1);
        __nv_bfloat16 l1 = __float2bfloat16(x1 - __bfloat162float(h1));
        uint32_t hp = (uint32_t)__bfloat16_as_ushort(h0) | ((uint32_t)__bfloat16_as_ushort(h1) << 16);
        uint32_t lp = (uint32_t)__bfloat16_as_ushort(l0) | ((uint32_t)__bfloat16_as_ushort(l1) << 16);
        *(uint32_t*)(row + ((kk2 * 4)      ^ xr)) = hp;
        *(uint32_t*)(row + ((64 + kk2 * 4) ^ xr)) = lp;
    }
}

__device__ __forceinline__ void cv_issw(int c, uint32_t stagebase, int tid)
{
#pragma unroll
    for (int i = 0; i < 4; i++) {
        int q = i * 512 + tid;
        int d = q >> 3, seg = q & 7;
        const __nv_bfloat16* s;
        uint32_t off;
        if (seg < 4) { s = g_Whi + (size_t)d * KTOT + c * 32 + seg * 8; off = (uint32_t)seg * 16u; }
        else         { s = g_Wlo + (size_t)d * KTOT + c * 32 + (seg - 4) * 8; off = 64u + (uint32_t)(seg - 4) * 16u; }
        uint32_t dst = stagebase + CWOFF + (uint32_t)d * 128u + (off ^ ((uint32_t)(d & 7) * 16u));
        cp_async16(dst, s);
    }
}

__global__ void __launch_bounds__(512, 1) conv_mma_kernel(
    const float* __restrict__ img_query, const float* __restrict__ img_supports)
{
    extern __shared__ __align__(128) char smem[];
    const int tid = threadIdx.x;
    const int l   = tid & 31, w = tid >> 5;
    const int pt  = blockIdx.x;                 // 0..3 (pos tiles of 128)
    const int img = blockIdx.y;                 // 0..207
    const float* src = (img < 8) ? (img_query + (size_t)img * IC * HH * WW)
                                 : (img_supports + (size_t)(img - 8) * IC * HH * WW);
    const int pbase = pt * 128;
    const int wm = (w >> 3) * 64;               // warp pos offset (0/64)
    const int wn = (w & 7) * 32;                // warp d offset (0..224)
    const uint32_t sbase = smem_u32(smem);

    // X loader per-thread state
    const int mp = tid & 127;
    const int h2 = tid >> 7;                    // 0..3
    const int p  = pbase + mp;
    const bool pvalid = (p < NPOS);
    const int r  = (p * 205) >> 12;             // p / 20 (valid p<4096)
    const int cc = p - r * 20;
    const float* rowbase = src + (size_t)(2 * r) * 41 + 2 * cc;
    int tS = 2 * h2, ciS = 0;                   // (k mod 9, k/9) for k = c*32 + 2*h2

    // ldmatrix per-lane row offsets + swizzle xors
    uint32_t arow[4], axor[4], brow[2], bxor[2];
#pragma unroll
    for (int mi = 0; mi < 4; mi++) {
        int rr = wm + mi * 16 + (l & 15);
        arow[mi] = (uint32_t)rr * 128u;
        axor[mi] = (uint32_t)(rr & 7) * 16u;
    }
#pragma unroll
    for (int ni2 = 0; ni2 < 2; ni2++) {
        int rr = wn + ni2 * 16 + (l & 7) + ((l >> 4) << 3);
        brow[ni2] = (uint32_t)rr * 128u;
        bxor[ni2] = (uint32_t)(rr & 7) * 16u;
    }
    const uint32_t ca0 = (uint32_t)((l >> 4) << 4);
    const uint32_t cb0 = (uint32_t)(((l >> 3) & 1) << 4);

    float acc[4][4][4];
#pragma unroll
    for (int mi = 0; mi < 4; mi++)
#pragma unroll
        for (int ni = 0; ni < 4; ni++)
#pragma unroll
            for (int q = 0; q < 4; q++) acc[mi][ni][q] = 0.f;

    float xv[8];
    // prologue: chunks 0 and 1
    cv_prefx(xv, rowbase, pvalid, tS, ciS);
    cv_issw(0, sbase + 0 * CSTG, tid);  CP_COMMIT();
    cv_stx(xv, smem + 0 * CSTG, mp, h2);
    tS += 5; ciS += 3; if (tS >= 9) { tS -= 9; ciS++; }
    cv_prefx(xv, rowbase, pvalid, tS, ciS);
    cv_issw(1, sbase + 1 * CSTG, tid);  CP_COMMIT();
    cv_stx(xv, smem + 1 * CSTG, mp, h2);
    tS += 5; ciS += 3; if (tS >= 9) { tS -= 9; ciS++; }

    int sidx = 0;
    for (int c = 0; c < NCH; c++) {
        CP_WAIT1();                 // stage c's W group complete
        __syncthreads();            // stage c's X stores + W visible; stage (c+2)%3 free

        const bool pf = (c + 2 < NCH);
        const int  ws = (sidx + 2 >= 3) ? (sidx - 1) : (sidx + 2);
        if (pf) {
            cv_prefx(xv, rowbase, pvalid, tS, ciS);
            tS += 5; ciS += 3; if (tS >= 9) { tS -= 9; ciS++; }
            cv_issw(c + 2, sbase + (uint32_t)ws * CSTG, tid);
        }
        CP_COMMIT();                // always (uniform group counting)

        const uint32_t sX = sbase + (uint32_t)sidx * CSTG + CXOFF;
        const uint32_t sW = sbase + (uint32_t)sidx * CSTG + CWOFF;

#pragma unroll
        for (int ks = 0; ks < 2; ks++) {
            const uint32_t colA = (uint32_t)(ks * 32) + ca0;
            const uint32_t colB = (uint32_t)(ks * 32) + cb0;
            uint32_t Ah[4][4], Bh[4][2], Bl[4][2], t4[4];

            // A hi
#pragma unroll
            for (int mi = 0; mi < 4; mi++)
                ldsm4(Ah[mi], sX + arow[mi] + (colA ^ axor[mi]));
            // B hi
#pragma unroll
            for (int ni2 = 0; ni2 < 2; ni2++) {
                ldsm4(t4, sW + brow[ni2] + (colB ^ bxor[ni2]));
                Bh[ni2 * 2][0] = t4[0];     Bh[ni2 * 2][1] = t4[1];
                Bh[ni2 * 2 + 1][0] = t4[2]; Bh[ni2 * 2 + 1][1] = t4[3];
            }
#pragma unroll
            for (int mi = 0; mi < 4; mi++)
#pragma unroll
                for (int ni = 0; ni < 4; ni++)
                    mma16816(acc[mi][ni], Ah[mi], Bh[ni]);

            // B lo
#pragma unroll
            for (int ni2 = 0; ni2 < 2; ni2++) {
                ldsm4(t4, sW + brow[ni2] + ((colB + 64) ^ bxor[ni2]));
                Bl[ni2 * 2][0] = t4[0];     Bl[ni2 * 2][1] = t4[1];
                Bl[ni2 * 2 + 1][0] = t4[2]; Bl[ni2 * 2 + 1][1] = t4[3];
            }
#pragma unroll
            for (int mi = 0; mi < 4; mi++)
#pragma unroll
                for (int ni = 0; ni < 4; ni++)
                    mma16816(acc[mi][ni], Ah[mi], Bl[ni]);

            // A lo (overwrite Ah), reuse Bh
#pragma unroll
            for (int mi = 0; mi < 4; mi++)
                ldsm4(Ah[mi], sX + arow[mi] + ((colA + 64) ^ axor[mi]));
#pragma unroll
            for (int mi = 0; mi < 4; mi++)
#pragma unroll
                for (int ni = 0; ni < 4; ni++)
                    mma16816(acc[mi][ni], Ah[mi], Bh[ni]);
        }

        if (pf) cv_stx(xv, smem + (size_t)ws * CSTG, mp, h2);
        sidx = (sidx + 1 >= 3) ? 0 : (sidx + 1);
    }

    // epilogue: C frag (p0 = l/4, d0 = 2*(l%4)) -> feats[img][d][p]
    const int prow = pbase + wm + (l >> 2);
    const int dcol = wn + 2 * (l & 3);
    float* fb = g_feats + (size_t)img * FSTRIDE;
#pragma unroll
    for (int mi = 0; mi < 4; mi++) {
        int p0 = prow + mi * 16;
#pragma unroll
        for (int ni = 0; ni < 4; ni++) {
            int d0 = dcol + ni * 8;
            if (p0 < NPOS) {
                fb[(size_t)d0 * NPOS + p0]       = acc[mi][ni][0];
                fb[(size_t)(d0 + 1) * NPOS + p0] = acc[mi][ni][1];
            }
            if (p0 + 8 < NPOS) {
                fb[(size_t)d0 * NPOS + p0 + 8]       = acc[mi][ni][2];
                fb[(size_t)(d0 + 1) * NPOS + p0 + 8] = acc[mi][ni][3];
            }
        }
    }
}

// ---------------- 3) sim GEMM (TN): C[m][j] = scale * sum_d Q[d][m] K[d][j] ----
__global__ void __launch_bounds__(256) gemm1_kernel()
{
    __shared__ __align__(16) float As[16 * 64];
    __shared__ __align__(16) float Bs[16 * 128];

    const int m0 = blockIdx.x * 64;
    const int j0 = blockIdx.y * 128;
    const int bk = blockIdx.z;
    const int b  = bk / 5;
    const size_t imgbase = (size_t)(8 + bk * 5) * FSTRIDE;
    const float scale = 0.08838834764831845f;   // 128^-0.5

    const int tid = threadIdx.x;
    const int tm = (tid >> 4) * 4;
    const int tj = (tid & 15) * 8;

    ull acc[4][4];
#pragma unroll
    for (int i = 0; i < 4; i++)
#pragma unroll
        for (int p = 0; p < 4; p++) acc[i][p] = 0ULL;

    for (int d0 = 0; d0 < 128; d0 += 16) {
        __syncthreads();
        for (int e = tid; e < 16 * 64; e += 256) {
            int dd = e >> 6, mm = e & 63;
            int m = m0 + mm;
            As[e] = (m < NPOS)
                  ? scale * g_feats[(size_t)b * FSTRIDE + (size_t)(d0 + dd) * NPOS + m]
                  : 0.f;
        }
        for (int e = tid; e < 16 * 128; e += 256) {
            int dd = e >> 7, jj = e & 127;
            int j = j0 + jj;
            float v = 0.f;
            if (j < NKEY) {
                int n = j / NPOS, jp = j - n * NPOS;
                v = g_feats[imgbase + (size_t)n * FSTRIDE + (size_t)(d0 + dd) * NPOS + jp];
            }
            Bs[e] = v;
        }
        __syncthreads();

#pragma unroll
        for (int dd = 0; dd < 16; dd++) {
            float4 a4 = *(const float4*)(As + dd * 64 + tm);
            ull a2[4];
            a2[0] = pack2(a4.x, a4.x); a2[1] = pack2(a4.y, a4.y);
            a2[2] = pack2(a4.z, a4.z); a2[3] = pack2(a4.w, a4.w);
            ull b2[4];
#pragma unroll
            for (int p = 0; p < 4; p++) b2[p] = *(const ull*)(Bs + dd * 128 + tj + 2 * p);
#pragma unroll
            for (int i = 0; i < 4; i++)
#pragma unroll
                for (int p = 0; p < 4; p++) ffma2(acc[i][p], a2[i], b2[p]);
        }
    }

#pragma unroll
    for (int i = 0; i < 4; i++) {
        int m = m0 + tm + i;
        if (m < NPOS) {
            float* cp = g_sim + (size_t)bk * (NPOS * NKEY) + (size_t)m * NKEY;
#pragma unroll
            for (int p = 0; p < 4; p++) {
                int j = j0 + tj + 2 * p;
                if (j < NKEY) *(ull*)(cp + j) = acc[i][p];
            }
        }
    }
}

// ---------------- 4) row softmax over 2000 ----------------
__global__ void __launch_bounds__(256) softmax_kernel()
{
    __shared__ float sred[8];
    const int row = blockIdx.x;
    float* p = g_sim + (size_t)row * NKEY;
    const int tid = threadIdx.x;

    float v[8];
    float mx = -1e30f;
#pragma unroll
    for (int i = 0; i < 8; i++) {
        int idx = tid + i * 256;
        v[i] = (idx < NKEY) ? p[idx] : -1e30f;
        mx = fmaxf(mx, v[i]);
    }
#pragma unroll
    for (int o = 16; o > 0; o >>= 1) mx = fmaxf(mx, __shfl_xor_sync(0xffffffffu, mx, o));
    if ((tid & 31) == 0) sred[tid >> 5] = mx;
    __syncthreads();
    float m0 = sred[0];
#pragma unroll
    for (int i = 1; i < 8; i++) m0 = fmaxf(m0, sred[i]);
    __syncthreads();

    float s = 0.f;
#pragma unroll
    for (int i = 0; i < 8; i++) {
        int idx = tid + i * 256;
        float e = (idx < NKEY) ? __expf(v[i] - m0) : 0.f;
        v[i] = e;
        s += e;
    }
#pragma unroll
    for (int o = 16; o > 0; o >>= 1) s += __shfl_xor_sync(0xffffffffu, s, o);
    if ((tid & 31) == 0) sred[tid >> 5] = s;
    __syncthreads();
    float tot = 0.f;
#pragma unroll
    for (int i = 0; i < 8; i++) tot += sred[i];
    float inv = 1.0f / tot;

#pragma unroll
    for (int i = 0; i < 8; i++) {
        int idx = tid + i * 256;
        if (idx < NKEY) p[idx] = v[i] * inv;
    }
}

// ---------------- 5) out GEMM (NT): Ot[c][m] = sum_kk V[c][kk] attn[m][kk] ----
__global__ void __launch_bounds__(256) gemm2_kernel()
{
    __shared__ __align__(16) float As[16 * 68];
    __shared__ __align__(16) float Bs[16 * 132];

    const int m0 = blockIdx.x * 128;
    const int c0 = blockIdx.y * 64;
    const int bk = blockIdx.z;
    const size_t imgbase = (size_t)(8 + bk * 5) * FSTRIDE;
    const float* attn = g_sim + (size_t)bk * (NPOS * NKEY);

    const int tid = threadIdx.x;
    const int tc = (tid >> 4) * 4;
    const int tm = (tid & 15) * 8;

    ull acc[4][4];
#pragma unroll
    for (int i = 0; i < 4; i++)
#pragma unroll
        for (int p = 0; p < 4; p++) acc[i][p] = 0ULL;

    for (int k0 = 0; k0 < NKEY; k0 += 16) {
        __syncthreads();
        {
            int n = k0 / NPOS, jp0 = k0 - n * NPOS;
            const float* vsrc = g_feats + imgbase + (size_t)n * FSTRIDE
                              + (size_t)(128 + c0) * NPOS + jp0;
            for (int e = tid; e < 64 * 16; e += 256) {
                int cc = e >> 4, kx = e & 15;
                As[kx * 68 + cc] = vsrc[(size_t)cc * NPOS + kx];
            }
        }
        for (int e = tid; e < 128 * 16; e += 256) {
            int mm = e >> 4, kx = e & 15;
            int m = m0 + mm;
            Bs[kx * 132 + mm] = (m < NPOS) ? attn[(size_t)m * NKEY + k0 + kx] : 0.f;
        }
        __syncthreads();

#pragma unroll
        for (int kx = 0; kx < 16; kx++) {
            float4 a4 = *(const float4*)(As + kx * 68 + tc);
            ull a2[4];
            a2[0] = pack2(a4.x, a4.x); a2[1] = pack2(a4.y, a4.y);
            a2[2] = pack2(a4.z, a4.z); a2[3] = pack2(a4.w, a4.w);
            ull b2[4];
#pragma unroll
            for (int p = 0; p < 4; p++) b2[p] = *(const ull*)(Bs + kx * 132 + tm + 2 * p);
#pragma unroll
            for (int i = 0; i < 4; i++)
#pragma unroll
                for (int p = 0; p < 4; p++) ffma2(acc[i][p], a2[i], b2[p]);
        }
    }

#pragma unroll
    for (int i = 0; i < 4; i++) {
        float* op = g_Ot + (size_t)bk * (128 * NPOS) + (size_t)(c0 + tc + i) * NPOS;
#pragma unroll
        for (int p = 0; p < 4; p++) {
            int m = m0 + tm + 2 * p;
            if (m < NPOS) *(ull*)(op + m) = acc[i][p];
        }
    }
}

// ---------------- 6) distance reduce ----------------
__global__ void __launch_bounds__(256) dist_kernel(float* __restrict__ out)
{
    __shared__ float sred[8];
    const int bk = blockIdx.x;
    const int b  = bk / 5;
    const float* qv = g_feats + (size_t)b * FSTRIDE + (size_t)128 * NPOS;
    const float* o  = g_Ot + (size_t)bk * (128 * NPOS);
    const int tid = threadIdx.x;

    float s = 0.f;
    for (int e = tid; e < 128 * NPOS; e += 256) {
        float d = qv[e] - o[e];
        s += d * d;
    }
#pragma unroll
    for (int off = 16; off > 0; off >>= 1) s += __shfl_xor_sync(0xffffffffu, s, off);
    if ((tid & 31) == 0) sred[tid >> 5] = s;
    __syncthreads();
    if (tid == 0) {
        float tot = 0.f;
#pragma unroll
        for (int i = 0; i < 8; i++) tot += sred[i];
        out[bk] = -tot * (1.0f / 400.0f);
    }
}

// ---------------------------------------------------------------------------
extern "C" void kernel_launch(void* const* d_in, const int* in_sizes, int n_in,
                              void* d_out, int out_size)
{
    const float* img_query    = (const float*)d_in[0];
    const float* img_supports = (const float*)d_in[1];
    const float* w_qk         = (const float*)d_in[2];
    const float* w_v          = (const float*)d_in[3];
    const float* w_ms         = (const float*)d_in[4];
    float* out = (float*)d_out;

    cudaFuncSetAttribute(conv_mma_kernel,
                         cudaFuncAttributeMaxDynamicSharedMemorySize, 3 * CSTG);

    fuse_kernel<<<288, 256>>>(w_qk, w_v, w_ms);
    conv_mma_kernel<<<dim3(4, NIMG), 512, 3 * CSTG>>>(img_query, img_supports);
    gemm1_kernel<<<dim3(7, 16, 40), 256>>>();
    softmax_kernel<<<16000, 256>>>();
    gemm2_kernel<<<dim3(4, 2, 40), 256>>>();
    dist_kernel<<<40, 256>>>(out);
}

// round 16
// speedup vs baseline: 1.7392x; 1.0049x over previous
#include <cuda_runtime.h>
#include <cuda_bf16.h>
#include <cstdint>

// ---------------------------------------------------------------------------
// MultiCrossTransformer on GB300 (sm_103a board, compute_103 virtual arch:
// NO tcgen05 — base-ISA mma.sync bf16 tensor path).
//
//  1) fuse_kernel : W[d][k] = sum_c proj[d][c]*w_ms[c][k], emitted bf16 hi/lo
//  2) conv_mma    : feats[img][d][400] = conv3x3_s2 via mma.sync implicit GEMM
//                   (bf16 3-term split: Wh*Xh + Wh*Xl + Wl*Xh, fp32 accum)
//  3) gemm1       : sim = scale * Q^T K        (f32x2 scalar)
//  4) softmax     : row softmax over 2000
//  5) gemm2       : Ot = V attn^T              (f32x2 scalar)
//  6) dist        : out[bk] = -||qv - Ot||^2 / 400
//  (two no-op launches positioned so ncu's capture window lands on conv_mma)
// ---------------------------------------------------------------------------

typedef unsigned long long ull;

#define IC    512
#define HH    41
#define WW    41
#define OHW   20
#define NPOS  400
#define NIMG  208
#define FSTRIDE 102400      // 256*400 floats per image
#define NKEY  2000
#define NBK   40
#define KTOT  4608          // 512*9

// scratch (device globals; no allocation APIs)
__device__ __nv_bfloat16 g_Whi[(size_t)256 * KTOT];   // [d][k]
__device__ __nv_bfloat16 g_Wlo[(size_t)256 * KTOT];
__device__ float g_feats[(size_t)NIMG * 256 * NPOS];
__device__ float g_sim[(size_t)NBK * NPOS * NKEY];
__device__ float g_Ot[(size_t)NBK * 128 * NPOS];

// ---------------- f32x2 helpers (scalar GEMMs) ----------------
__device__ __forceinline__ void ffma2(ull& d, ull a, ull b) {
    asm("fma.rn.f32x2 %0, %1, %2, %0;" : "+l"(d) : "l"(a), "l"(b));
}
__device__ __forceinline__ ull pack2(float x, float y) {
    ull r; asm("mov.b64 %0, {%1, %2};" : "=l"(r) : "f"(x), "f"(y)); return r;
}

// ---------------- mma.sync / ldmatrix / cp.async helpers (base ISA) --------
__device__ __forceinline__ uint32_t smem_u32(const void* p) {
    uint32_t a;
    asm("{ .reg .u64 t; cvta.to.shared.u64 t, %1; cvt.u32.u64 %0, t; }" : "=r"(a) : "l"(p));
    return a;
}
__device__ __forceinline__ void ldsm4(uint32_t* r, uint32_t a) {
    asm volatile("ldmatrix.sync.aligned.m8n8.x4.shared.b16 {%0,%1,%2,%3}, [%4];"
        : "=r"(r[0]), "=r"(r[1]), "=r"(r[2]), "=r"(r[3]) : "r"(a));
}
__device__ __forceinline__ void mma16816(float* d, const uint32_t* a, const uint32_t* b) {
    asm volatile(
        "mma.sync.aligned.m16n8k16.row.col.f32.bf16.bf16.f32 "
        "{%0,%1,%2,%3}, {%4,%5,%6,%7}, {%8,%9}, {%0,%1,%2,%3};"
        : "+f"(d[0]), "+f"(d[1]), "+f"(d[2]), "+f"(d[3])
        : "r"(a[0]), "r"(a[1]), "r"(a[2]), "r"(a[3]), "r"(b[0]), "r"(b[1]));
}
__device__ __forceinline__ void cp_async16(uint32_t dst, const void* src) {
    asm volatile("cp.async.cg.shared.global [%0], [%1], 16;" :: "r"(dst), "l"(src));
}
#define CP_COMMIT() asm volatile("cp.async.commit_group;" ::: "memory")
#define CP_WAIT1()  asm volatile("cp.async.wait_group 1;" ::: "memory")

// ---------------- profiling-slot alignment ----------------
__global__ void dummy_kernel() {}

// ---------------- 1) weight fusion -> bf16 hi/lo, [d][k] layout ----------------
__global__ void __launch_bounds__(256) fuse_kernel(
    const float* __restrict__ w_qk, const float* __restrict__ w_v,
    const float* __restrict__ w_ms)
{
    __shared__ __align__(16) float wcol[512 * 16];   // [c][t]
    int k0 = blockIdx.x * 16;
    int d  = threadIdx.x;

    for (int e = d; e < 512 * 16; e += 256) {
        int c = e >> 4, t = e & 15;
        wcol[e] = w_ms[(size_t)c * KTOT + k0 + t];
    }
    __syncthreads();

    const float4* proj4 = (const float4*)((d < 128) ? (w_qk + (size_t)d * 512)
                                                    : (w_v  + (size_t)(d - 128) * 512));
    float acc[16];
#pragma unroll
    for (int t = 0; t < 16; t++) acc[t] = 0.f;

    for (int c4 = 0; c4 < 128; c4++) {
        float4 p = proj4[c4];
#pragma unroll
        for (int q = 0; q < 4; q++) {
            float pv = (q == 0) ? p.x : (q == 1) ? p.y : (q == 2) ? p.z : p.w;
            const float4* wf = (const float4*)(wcol + (c4 * 4 + q) * 16);
            float4 b0 = wf[0], b1 = wf[1], b2 = wf[2], b3 = wf[3];
            acc[0]  += pv * b0.x;  acc[1]  += pv * b0.y;
            acc[2]  += pv * b0.z;  acc[3]  += pv * b0.w;
            acc[4]  += pv * b1.x;  acc[5]  += pv * b1.y;
            acc[6]  += pv * b1.z;  acc[7]  += pv * b1.w;
            acc[8]  += pv * b2.x;  acc[9]  += pv * b2.y;
            acc[10] += pv * b2.z;  acc[11] += pv * b2.w;
            acc[12] += pv * b3.x;  acc[13] += pv * b3.y;
            acc[14] += pv * b3.z;  acc[15] += pv * b3.w;
        }
    }
#pragma unroll
    for (int t = 0; t < 16; t++) {
        float a = acc[t];
        __nv_bfloat16 h = __float2bfloat16(a);
        __nv_bfloat16 l = __float2bfloat16(a - __bfloat162float(h));
        g_Whi[(size_t)d * KTOT + k0 + t] = h;
        g_Wlo[(size_t)d * KTOT + k0 + t] = l;
    }
}

// ---------------- 2) conv via mma.sync bf16-split implicit GEMM ----------------
// C[p][d] = sum_k X[p][k] * W[k][d]; 512 threads, CTA tile 128p x 256d.
// 16 warps as 2(m) x 8(n); warp tile 64p x 32d. K = 4608 in 144 chunks of 32.
// Stage: X 128x128B rows (32 k hi | 32 k lo, swizzled) + W 256x128B rows.
#define NCH    144
#define CSTG   49152
#define CXOFF  0
#define CWOFF  16384

__device__ __forceinline__ void cv_prefx(
    float* xv, const float* __restrict__ rowbase, bool pvalid, int tS, int ciS)
{
    int tl = tS, cil = ciS;
#pragma unroll
    for (int i = 0; i < 4; i++) {
        float x0 = 0.f, x1 = 0.f;
        if (pvalid) {
            int th = (tl * 11) >> 5;
            x0 = rowbase[cil * 1681 + th * 41 + (tl - 3 * th)];
            int t1 = tl + 1, c1 = cil;
            if (t1 == 9) { t1 = 0; c1++; }
            int th1 = (t1 * 11) >> 5;
            x1 = rowbase[c1 * 1681 + th1 * 41 + (t1 - 3 * th1)];
        }
        xv[2 * i] = x0; xv[2 * i + 1] = x1;
        tl += 8; if (tl >= 9) { tl -= 9; cil++; }
    }
}

__device__ __forceinline__ void cv_stx(const float* xv, char* stage, int mp, int h2)
{
    uint32_t xr = (uint32_t)(mp & 7) * 16u;
    char* row = stage + CXOFF + (uint32_t)mp * 128u;
#pragma unroll
    for (int i = 0; i < 4; i++) {
        int kk2 = i * 4 + h2;
        float x0 = xv[2 * i], x1 = xv[2 * i + 1];
        __nv_bfloat16 h0 = __float2bfloat16(x0);
        __nv_bfloat16 l0 = __float2bfloat16(x0 - __bfloat162float(h0));
        __nv_bfloat16 h1 = __float2bfloat16(x1);
        __nv_bfloat16 l1 = __float2bfloat16(x1 - __bfloat162float(h1));
        uint32_t hp = (uint32_t)__bfloat16_as_ushort(h0) | ((uint32_t)__bfloat16_as_ushort(h1) << 16);
        uint32_t lp = (uint32_t)__bfloat16_as_ushort(l0) | ((uint32_t)__bfloat16_as_ushort(l1) << 16);
        *(uint32_t*)(row + ((kk2 * 4)      ^ xr)) = hp;
        *(uint32_t*)(row + ((64 + kk2 * 4) ^ xr)) = lp;
    }
}

__device__ __forceinline__ void cv_issw(int c, uint32_t stagebase, int tid)
{
#pragma unroll
    for (int i = 0; i < 4; i++) {
        int q = i * 512 + tid;
        int d = q >> 3, seg = q & 7;
        const __nv_bfloat16* s;
        uint32_t off;
        if (seg < 4) { s = g_Whi + (size_t)d * KTOT + c * 32 + seg * 8; off = (uint32_t)seg * 16u; }
        else         { s = g_Wlo + (size_t)d * KTOT + c * 32 + (seg - 4) * 8; off = 64u + (uint32_t)(seg - 4) * 16u; }
        uint32_t dst = stagebase + CWOFF + (uint32_t)d * 128u + (off ^ ((uint32_t)(d & 7) * 16u));
        cp_async16(dst, s);
    }
}

__global__ void __launch_bounds__(512, 1) conv_mma_kernel(
    const float* __restrict__ img_query, const float* __restrict__ img_supports)
{
    extern __shared__ __align__(128) char smem[];
    const int tid = threadIdx.x;
    const int l   = tid & 31, w = tid >> 5;
    const int pt  = blockIdx.x;                 // 0..3 (pos tiles of 128)
    const int img = blockIdx.y;                 // 0..207
    const float* src = (img < 8) ? (img_query + (size_t)img * IC * HH * WW)
                                 : (img_supports + (size_t)(img - 8) * IC * HH * WW);
    const int pbase = pt * 128;
    const int wm = (w >> 3) * 64;               // warp pos offset (0/64)
    const int wn = (w & 7) * 32;                // warp d offset (0..224)
    const uint32_t sbase = smem_u32(smem);

    // X loader per-thread state
    const int mp = tid & 127;
    const int h2 = tid >> 7;                    // 0..3
    const int p  = pbase + mp;
    const bool pvalid = (p < NPOS);
    const int r  = (p * 205) >> 12;             // p / 20 (valid p<4096)
    const int cc = p - r * 20;
    const float* rowbase = src + (size_t)(2 * r) * 41 + 2 * cc;
    int tS = 2 * h2, ciS = 0;                   // (k mod 9, k/9) for k = c*32 + 2*h2

    // ldmatrix addressing: swizzle xor is identical for all tiles of this lane
    // ((wm|wn, mi*16, ni2*16, (l>>4)<<3 are all multiples of 8) -> rr&7 == l&7)
    const uint32_t xr    = (uint32_t)(l & 7) * 16u;
    const uint32_t arow0 = (uint32_t)(wm + (l & 15)) * 128u;
    const uint32_t brow0 = (uint32_t)(wn + (l & 7) + ((l >> 4) << 3)) * 128u;
    const uint32_t ca0 = (uint32_t)((l >> 4) << 4);
    const uint32_t cb0 = (uint32_t)(((l >> 3) & 1) << 4);

    float acc[4][4][4];
#pragma unroll
    for (int mi = 0; mi < 4; mi++)
#pragma unroll
        for (int ni = 0; ni < 4; ni++)
#pragma unroll
            for (int q = 0; q < 4; q++) acc[mi][ni][q] = 0.f;

    float xv[8];
    // prologue: chunks 0 and 1
    cv_prefx(xv, rowbase, pvalid, tS, ciS);
    cv_issw(0, sbase + 0 * CSTG, tid);  CP_COMMIT();
    cv_stx(xv, smem + 0 * CSTG, mp, h2);
    tS += 5; ciS += 3; if (tS >= 9) { tS -= 9; ciS++; }
    cv_prefx(xv, rowbase, pvalid, tS, ciS);
    cv_issw(1, sbase + 1 * CSTG, tid);  CP_COMMIT();
    cv_stx(xv, smem + 1 * CSTG, mp, h2);
    tS += 5; ciS += 3; if (tS >= 9) { tS -= 9; ciS++; }

    int sidx = 0;
    for (int c = 0; c < NCH; c++) {
        CP_WAIT1();                 // stage c's W group complete
        __syncthreads();            // stage c's X stores + W visible; stage (c+2)%3 free

        const bool pf = (c + 2 < NCH);
        const int  ws = (sidx + 2 >= 3) ? (sidx - 1) : (sidx + 2);
        if (pf) {
            cv_prefx(xv, rowbase, pvalid, tS, ciS);
            tS += 5; ciS += 3; if (tS >= 9) { tS -= 9; ciS++; }
            cv_issw(c + 2, sbase + (uint32_t)ws * CSTG, tid);
        }
        CP_COMMIT();                // always (uniform group counting)

        const uint32_t sX = sbase + (uint32_t)sidx * CSTG + CXOFF;
        const uint32_t sW = sbase + (uint32_t)sidx * CSTG + CWOFF;

#pragma unroll
        for (int ks = 0; ks < 2; ks++) {
            const uint32_t colA = (uint32_t)(ks * 32) + ca0;
            const uint32_t colB = (uint32_t)(ks * 32) + cb0;
            uint32_t Ah[4][4], Bh[4][2], Bl[4][2], t4[4];

            // A hi
#pragma unroll
            for (int mi = 0; mi < 4; mi++)
                ldsm4(Ah[mi], sX + (arow0 + (uint32_t)mi * 2048u) + (colA ^ xr));
            // B hi
#pragma unroll
            for (int ni2 = 0; ni2 < 2; ni2++) {
                ldsm4(t4, sW + (brow0 + (uint32_t)ni2 * 2048u) + (colB ^ xr));
                Bh[ni2 * 2][0] = t4[0];     Bh[ni2 * 2][1] = t4[1];
                Bh[ni2 * 2 + 1][0] = t4[2]; Bh[ni2 * 2 + 1][1] = t4[3];
            }
#pragma unroll
            for (int mi = 0; mi < 4; mi++)
#pragma unroll
                for (int ni = 0; ni < 4; ni++)
                    mma16816(acc[mi][ni], Ah[mi], Bh[ni]);

            // B lo
#pragma unroll
            for (int ni2 = 0; ni2 < 2; ni2++) {
                ldsm4(t4, sW + (brow0 + (uint32_t)ni2 * 2048u) + ((colB + 64) ^ xr));
                Bl[ni2 * 2][0] = t4[0];     Bl[ni2 * 2][1] = t4[1];
                Bl[ni2 * 2 + 1][0] = t4[2]; Bl[ni2 * 2 + 1][1] = t4[3];
            }
#pragma unroll
            for (int mi = 0; mi < 4; mi++)
#pragma unroll
                for (int ni = 0; ni < 4; ni++)
                    mma16816(acc[mi][ni], Ah[mi], Bl[ni]);

            // A lo (overwrite Ah), reuse Bh
#pragma unroll
            for (int mi = 0; mi < 4; mi++)
                ldsm4(Ah[mi], sX + (arow0 + (uint32_t)mi * 2048u) + ((colA + 64) ^ xr));
#pragma unroll
            for (int mi = 0; mi < 4; mi++)
#pragma unroll
                for (int ni = 0; ni < 4; ni++)
                    mma16816(acc[mi][ni], Ah[mi], Bh[ni]);
        }

        if (pf) cv_stx(xv, smem + (size_t)ws * CSTG, mp, h2);
        sidx = (sidx + 1 >= 3) ? 0 : (sidx + 1);
    }

    // epilogue: C frag (p0 = l/4, d0 = 2*(l%4)) -> feats[img][d][p]
    const int prow = pbase + wm + (l >> 2);
    const int dcol = wn + 2 * (l & 3);
    float* fb = g_feats + (size_t)img * FSTRIDE;
#pragma unroll
    for (int mi = 0; mi < 4; mi++) {
        int p0 = prow + mi * 16;
#pragma unroll
        for (int ni = 0; ni < 4; ni++) {
            int d0 = dcol + ni * 8;
            if (p0 < NPOS) {
                fb[(size_t)d0 * NPOS + p0]       = acc[mi][ni][0];
                fb[(size_t)(d0 + 1) * NPOS + p0] = acc[mi][ni][1];
            }
            if (p0 + 8 < NPOS) {
                fb[(size_t)d0 * NPOS + p0 + 8]       = acc[mi][ni][2];
                fb[(size_t)(d0 + 1) * NPOS + p0 + 8] = acc[mi][ni][3];
            }
        }
    }
}

// ---------------- 3) sim GEMM (TN): C[m][j] = scale * sum_d Q[d][m] K[d][j] ----
__global__ void __launch_bounds__(256) gemm1_kernel()
{
    __shared__ __align__(16) float As[16 * 64];
    __shared__ __align__(16) float Bs[16 * 128];

    const int m0 = blockIdx.x * 64;
    const int j0 = blockIdx.y * 128;
    const int bk = blockIdx.z;
    const int b  = bk / 5;
    const size_t imgbase = (size_t)(8 + bk * 5) * FSTRIDE;
    const float scale = 0.08838834764831845f;   // 128^-0.5

    const int tid = threadIdx.x;
    const int tm = (tid >> 4) * 4;
    const int tj = (tid & 15) * 8;

    ull acc[4][4];
#pragma unroll
    for (int i = 0; i < 4; i++)
#pragma unroll
        for (int p = 0; p < 4; p++) acc[i][p] = 0ULL;

    for (int d0 = 0; d0 < 128; d0 += 16) {
        __syncthreads();
        for (int e = tid; e < 16 * 64; e += 256) {
            int dd = e >> 6, mm = e & 63;
            int m = m0 + mm;
            As[e] = (m < NPOS)
                  ? scale * g_feats[(size_t)b * FSTRIDE + (size_t)(d0 + dd) * NPOS + m]
                  : 0.f;
        }
        for (int e = tid; e < 16 * 128; e += 256) {
            int dd = e >> 7, jj = e & 127;
            int j = j0 + jj;
            float v = 0.f;
            if (j < NKEY) {
                int n = j / NPOS, jp = j - n * NPOS;
                v = g_feats[imgbase + (size_t)n * FSTRIDE + (size_t)(d0 + dd) * NPOS + jp];
            }
            Bs[e] = v;
        }
        __syncthreads();

#pragma unroll
        for (int dd = 0; dd < 16; dd++) {
            float4 a4 = *(const float4*)(As + dd * 64 + tm);
            ull a2[4];
            a2[0] = pack2(a4.x, a4.x); a2[1] = pack2(a4.y, a4.y);
            a2[2] = pack2(a4.z, a4.z); a2[3] = pack2(a4.w, a4.w);
            ull b2[4];
#pragma unroll
            for (int p = 0; p < 4; p++) b2[p] = *(const ull*)(Bs + dd * 128 + tj + 2 * p);
#pragma unroll
            for (int i = 0; i < 4; i++)
#pragma unroll
                for (int p = 0; p < 4; p++) ffma2(acc[i][p], a2[i], b2[p]);
        }
    }

#pragma unroll
    for (int i = 0; i < 4; i++) {
        int m = m0 + tm + i;
        if (m < NPOS) {
            float* cp = g_sim + (size_t)bk * (NPOS * NKEY) + (size_t)m * NKEY;
#pragma unroll
            for (int p = 0; p < 4; p++) {
                int j = j0 + tj + 2 * p;
                if (j < NKEY) *(ull*)(cp + j) = acc[i][p];
            }
        }
    }
}

// ---------------- 4) row softmax over 2000 ----------------
__global__ void __launch_bounds__(256) softmax_kernel()
{
    __shared__ float sred[8];
    const int row = blockIdx.x;
    float* p = g_sim + (size_t)row * NKEY;
    const int tid = threadIdx.x;

    float v[8];
    float mx = -1e30f;
#pragma unroll
    for (int i = 0; i < 8; i++) {
        int idx = tid + i * 256;
        v[i] = (idx < NKEY) ? p[idx] : -1e30f;
        mx = fmaxf(mx, v[i]);
    }
#pragma unroll
    for (int o = 16; o > 0; o >>= 1) mx = fmaxf(mx, __shfl_xor_sync(0xffffffffu, mx, o));
    if ((tid & 31) == 0) sred[tid >> 5] = mx;
    __syncthreads();
    float m0 = sred[0];
#pragma unroll
    for (int i = 1; i < 8; i++) m0 = fmaxf(m0, sred[i]);
    __syncthreads();

    float s = 0.f;
#pragma unroll
    for (int i = 0; i < 8; i++) {
        int idx = tid + i * 256;
        float e = (idx < NKEY) ? __expf(v[i] - m0) : 0.f;
        v[i] = e;
        s += e;
    }
#pragma unroll
    for (int o = 16; o > 0; o >>= 1) s += __shfl_xor_sync(0xffffffffu, s, o);
    if ((tid & 31) == 0) sred[tid >> 5] = s;
    __syncthreads();
    float tot = 0.f;
#pragma unroll
    for (int i = 0; i < 8; i++) tot += sred[i];
    float inv = 1.0f / tot;

#pragma unroll
    for (int i = 0; i < 8; i++) {
        int idx = tid + i * 256;
        if (idx < NKEY) p[idx] = v[i] * inv;
    }
}

// ---------------- 5) out GEMM (NT): Ot[c][m] = sum_kk V[c][kk] attn[m][kk] ----
__global__ void __launch_bounds__(256) gemm2_kernel()
{
    __shared__ __align__(16) float As[16 * 68];
    __shared__ __align__(16) float Bs[16 * 132];

    const int m0 = blockIdx.x * 128;
    const int c0 = blockIdx.y * 64;
    const int bk = blockIdx.z;
    const size_t imgbase = (size_t)(8 + bk * 5) * FSTRIDE;
    const float* attn = g_sim + (size_t)bk * (NPOS * NKEY);

    const int tid = threadIdx.x;
    const int tc = (tid >> 4) * 4;
    const int tm = (tid & 15) * 8;

    ull acc[4][4];
#pragma unroll
    for (int i = 0; i < 4; i++)
#pragma unroll
        for (int p = 0; p < 4; p++) acc[i][p] = 0ULL;

    for (int k0 = 0; k0 < NKEY; k0 += 16) {
        __syncthreads();
        {
            int n = k0 / NPOS, jp0 = k0 - n * NPOS;
            const float* vsrc = g_feats + imgbase + (size_t)n * FSTRIDE
                              + (size_t)(128 + c0) * NPOS + jp0;
            for (int e = tid; e < 64 * 16; e += 256) {
                int cc = e >> 4, kx = e & 15;
                As[kx * 68 + cc] = vsrc[(size_t)cc * NPOS + kx];
            }
        }
        for (int e = tid; e < 128 * 16; e += 256) {
            int mm = e >> 4, kx = e & 15;
            int m = m0 + mm;
            Bs[kx * 132 + mm] = (m < NPOS) ? attn[(size_t)m * NKEY + k0 + kx] : 0.f;
        }
        __syncthreads();

#pragma unroll
        for (int kx = 0; kx < 16; kx++) {
            float4 a4 = *(const float4*)(As + kx * 68 + tc);
            ull a2[4];
            a2[0] = pack2(a4.x, a4.x); a2[1] = pack2(a4.y, a4.y);
            a2[2] = pack2(a4.z, a4.z); a2[3] = pack2(a4.w, a4.w);
            ull b2[4];
#pragma unroll
            for (int p = 0; p < 4; p++) b2[p] = *(const ull*)(Bs + kx * 132 + tm + 2 * p);
#pragma unroll
            for (int i = 0; i < 4; i++)
#pragma unroll
                for (int p = 0; p < 4; p++) ffma2(acc[i][p], a2[i], b2[p]);
        }
    }

#pragma unroll
    for (int i = 0; i < 4; i++) {
        float* op = g_Ot + (size_t)bk * (128 * NPOS) + (size_t)(c0 + tc + i) * NPOS;
#pragma unroll
        for (int p = 0; p < 4; p++) {
            int m = m0 + tm + 2 * p;
            if (m < NPOS) *(ull*)(op + m) = acc[i][p];
        }
    }
}

// ---------------- 6) distance reduce ----------------
__global__ void __launch_bounds__(256) dist_kernel(float* __restrict__ out)
{
    __shared__ float sred[8];
    const int bk = blockIdx.x;
    const int b  = bk / 5;
    const float* qv = g_feats + (size_t)b * FSTRIDE + (size_t)128 * NPOS;
    const float* o  = g_Ot + (size_t)bk * (128 * NPOS);
    const int tid = threadIdx.x;

    float s = 0.f;
    for (int e = tid; e < 128 * NPOS; e += 256) {
        float d = qv[e] - o[e];
        s += d * d;
    }
#pragma unroll
    for (int off = 16; off > 0; off >>= 1) s += __shfl_xor_sync(0xffffffffu, s, off);
    if ((tid & 31) == 0) sred[tid >> 5] = s;
    __syncthreads();
    if (tid == 0) {
        float tot = 0.f;
#pragma unroll
        for (int i = 0; i < 8; i++) tot += sred[i];
        out[bk] = -tot * (1.0f / 400.0f);
    }
}

// ---------------------------------------------------------------------------
extern "C" void kernel_launch(void* const* d_in, const int* in_sizes, int n_in,
                              void* d_out, int out_size)
{
    const float* img_query    = (const float*)d_in[0];
    const float* img_supports = (const float*)d_in[1];
    const float* w_qk         = (const float*)d_in[2];
    const float* w_v          = (const float*)d_in[3];
    const float* w_ms         = (const float*)d_in[4];
    float* out = (float*)d_out;

    cudaFuncSetAttribute(conv_mma_kernel,
                         cudaFuncAttributeMaxDynamicSharedMemorySize, 3 * CSTG);

    fuse_kernel<<<288, 256>>>(w_qk, w_v, w_ms);
    dummy_kernel<<<1, 32>>>();      // shift conv into ncu's capture slot
    dummy_kernel<<<1, 32>>>();      // (slot that previously caught softmax)
    conv_mma_kernel<<<dim3(4, NIMG), 512, 3 * CSTG>>>(img_query, img_supports);
    gemm1_kernel<<<dim3(7, 16, 40), 256>>>();
    softmax_kernel<<<16000, 256>>>();
    gemm2_kernel<<<dim3(4, 2, 40), 256>>>();
    dist_kernel<<<40, 256>>>(out);
}